// round 1
// baseline (speedup 1.0000x reference)
#include <cuda_runtime.h>

#define NIMG  4
#define KCH   21
#define HO    64
#define WO    64
#define NPIX  4096      // HO*WO
#define TILE  128
#define NT    32        // NPIX / TILE
#define NPAIR 528       // NT*(NT+1)/2
#define HW    16384     // 128*128

// Scratch (device globals; no allocation in kernel_launch)
__device__ float g_sroi[NIMG][KCH][NPIX];   // seg (2x2 avg) * roi
__device__ float g_feat[NIMG][5][NPIX];     // x/50, y/50, r/15, g/15, b/15
__device__ float g_sq  [NIMG][NPIX];        // |f|^2
__device__ float g_gate[NIMG][NPIX];
__device__ float g_partial[NIMG * NPAIR];

// ---------------------------------------------------------------------------
// Kernel 1: fused downscale + gate + features. One thread per (n, p).
// ---------------------------------------------------------------------------
__global__ void prep_kernel(const float* __restrict__ images,
                            const float* __restrict__ segs,
                            const float* __restrict__ rois,
                            const int*   __restrict__ labels)
{
    int idx = blockIdx.x * blockDim.x + threadIdx.x;
    if (idx >= NIMG * NPIX) return;
    int n = idx >> 12;
    int p = idx & (NPIX - 1);
    int y = p >> 6, x = p & 63;
    int src = (2*y) * 128 + (2*x);

    float roi = rois[n * HW + src];

    const float* sb = segs + (size_t)n * KCH * HW + src;
    float mx = -1e30f;
    #pragma unroll
    for (int k = 0; k < KCH; k++) {
        const float* sp = sb + (size_t)k * HW;
        float v = 0.25f * (sp[0] + sp[1] + sp[128] + sp[129]);  // exact bilinear 2x
        mx = fmaxf(mx, v);
        g_sroi[n][k][p] = v * roi;
    }

    int lbl = labels[n * HW + src];
    float gate = (lbl == 255) ? 1.0f : (roi - mx);
    gate = fmaxf(gate, 0.0f);
    g_gate[n][p] = gate;

    const float* ib = images + (size_t)n * 3 * HW + src;
    float fx = (float)x * (1.0f / 50.0f);   // SIGMA_XY * SCALE = 50
    float fy = (float)y * (1.0f / 50.0f);
    float r  = ib[0]      * (1.0f / 15.0f);
    float g  = ib[HW]     * (1.0f / 15.0f);
    float b  = ib[2 * HW] * (1.0f / 15.0f);
    g_feat[n][0][p] = fx; g_feat[n][1][p] = fy;
    g_feat[n][2][p] = r;  g_feat[n][3][p] = g; g_feat[n][4][p] = b;
    g_sq[n][p] = fx*fx + fy*fy + r*r + g*g + b*b;
}

// ---------------------------------------------------------------------------
// Kernel 2: tiled bilateral energy over the upper triangle of (p,q) tiles.
// CTA = (tile-pair t, image n). 256 threads, each owns an 8x8 pair block with
// interleaved mapping p = ty + 16*i, q = tx + 16*j (conflict-free LDS).
// Off-diagonal tiles use symmetry: weight (g_p + g_q). Diagonal tiles: full
// sum with weight g_p (covers p=q and both orderings exactly).
// ---------------------------------------------------------------------------
__global__ __launch_bounds__(256, 2) void energy_kernel()
{
    __shared__ float sP[KCH][TILE], sQ[KCH][TILE];
    __shared__ float fP[5][TILE],  fQ[5][TILE];
    __shared__ float sqP[TILE], sqQ[TILE], gP[TILE], gQ[TILE];
    __shared__ float red[8];

    int t = blockIdx.x;
    int n = blockIdx.y;

    // triangular decode (uniform per block)
    int ti = 0, rem = t;
    while (rem >= NT - ti) { rem -= NT - ti; ti++; }
    int tj = ti + rem;
    int p0 = ti * TILE, q0 = tj * TILE;
    bool diag = (ti == tj);

    int tid = threadIdx.x;
    for (int i = tid; i < KCH * TILE; i += 256) {
        int k = i >> 7, pp = i & 127;
        sP[k][pp] = g_sroi[n][k][p0 + pp];
        sQ[k][pp] = g_sroi[n][k][q0 + pp];
    }
    for (int i = tid; i < 5 * TILE; i += 256) {
        int d = i >> 7, pp = i & 127;
        fP[d][pp] = g_feat[n][d][p0 + pp];
        fQ[d][pp] = g_feat[n][d][q0 + pp];
    }
    if (tid < TILE) {
        sqP[tid] = g_sq[n][p0 + tid];   sqQ[tid] = g_sq[n][q0 + tid];
        gP[tid]  = g_gate[n][p0 + tid]; gQ[tid]  = g_gate[n][q0 + tid];
    }
    __syncthreads();

    int tx = tid & 15, ty = tid >> 4;

    // ---- Phase 1: 5-D feature dot products ----
    float w[8][8];
    #pragma unroll
    for (int i = 0; i < 8; i++)
        #pragma unroll
        for (int j = 0; j < 8; j++) w[i][j] = 0.0f;

    #pragma unroll
    for (int d = 0; d < 5; d++) {
        float a[8], b[8];
        #pragma unroll
        for (int i = 0; i < 8; i++) a[i] = fP[d][ty + 16*i];
        #pragma unroll
        for (int j = 0; j < 8; j++) b[j] = fQ[d][tx + 16*j];
        #pragma unroll
        for (int i = 0; i < 8; i++)
            #pragma unroll
            for (int j = 0; j < 8; j++) w[i][j] = fmaf(a[i], b[j], w[i][j]);
    }

    // ---- Phase 2: convert dots -> exp(-0.5*d2) * gate-coefficient in place ----
    {
        float sp_[8], sq_[8], gp_[8], gq_[8];
        #pragma unroll
        for (int i = 0; i < 8; i++) { sp_[i] = sqP[ty + 16*i]; gp_[i] = gP[ty + 16*i]; }
        #pragma unroll
        for (int j = 0; j < 8; j++) { sq_[j] = sqQ[tx + 16*j]; gq_[j] = gQ[tx + 16*j]; }
        #pragma unroll
        for (int i = 0; i < 8; i++) {
            #pragma unroll
            for (int j = 0; j < 8; j++) {
                float d2 = fmaxf(sp_[i] + sq_[j] - 2.0f * w[i][j], 0.0f);
                float coef = diag ? gp_[i] : (gp_[i] + gq_[j]);
                w[i][j] = __expf(-0.5f * d2) * coef;
            }
        }
    }

    // ---- Phase 3: fold in the K=21 segmentation dot: acc += a_i * (w_ij . b_j) ----
    float acc0 = 0.0f, acc1 = 0.0f, acc2 = 0.0f, acc3 = 0.0f;
    #pragma unroll 3
    for (int k = 0; k < KCH; k++) {
        float a[8], b[8];
        #pragma unroll
        for (int i = 0; i < 8; i++) a[i] = sP[k][ty + 16*i];
        #pragma unroll
        for (int j = 0; j < 8; j++) b[j] = sQ[k][tx + 16*j];
        #pragma unroll
        for (int i = 0; i < 8; i++) {
            float inner = 0.0f;
            #pragma unroll
            for (int j = 0; j < 8; j++) inner = fmaf(w[i][j], b[j], inner);
            float v = a[i] * inner;
            if ((i & 3) == 0) acc0 += v;
            else if ((i & 3) == 1) acc1 += v;
            else if ((i & 3) == 2) acc2 += v;
            else acc3 += v;
        }
    }
    float acc = (acc0 + acc1) + (acc2 + acc3);

    // ---- block reduction, deterministic per-CTA partial ----
    #pragma unroll
    for (int o = 16; o > 0; o >>= 1) acc += __shfl_down_sync(0xffffffffu, acc, o);
    if ((tid & 31) == 0) red[tid >> 5] = acc;
    __syncthreads();
    if (tid == 0) {
        float s = 0.0f;
        #pragma unroll
        for (int v = 0; v < 8; v++) s += red[v];
        g_partial[n * NPAIR + t] = s;
    }
}

// ---------------------------------------------------------------------------
// Kernel 3: deterministic final reduction + scaling.
// ---------------------------------------------------------------------------
__global__ void reduce_kernel(float* __restrict__ out)
{
    __shared__ float red[8];
    int tid = threadIdx.x;
    float s = 0.0f;
    for (int i = tid; i < NIMG * NPAIR; i += 256) s += g_partial[i];
    #pragma unroll
    for (int o = 16; o > 0; o >>= 1) s += __shfl_down_sync(0xffffffffu, s, o);
    if ((tid & 31) == 0) red[tid >> 5] = s;
    __syncthreads();
    if (tid == 0) {
        float tot = 0.0f;
        #pragma unroll
        for (int v = 0; v < 8; v++) tot += red[v];
        out[0] = tot * (-1e-7f / (float)NIMG);   // WEIGHT * (-sum / N)
    }
}

// ---------------------------------------------------------------------------
extern "C" void kernel_launch(void* const* d_in, const int* in_sizes, int n_in,
                              void* d_out, int out_size)
{
    const float* images = (const float*)d_in[0];   // [4,3,128,128]
    const float* segs   = (const float*)d_in[1];   // [4,21,128,128]
    const float* rois   = (const float*)d_in[2];   // [4,128,128]
    const int*   labels = (const int*)  d_in[3];   // [4,1,128,128]

    prep_kernel<<<(NIMG * NPIX + 255) / 256, 256>>>(images, segs, rois, labels);
    dim3 grid(NPAIR, NIMG);
    energy_kernel<<<grid, 256>>>();
    reduce_kernel<<<1, 256>>>((float*)d_out);
}